// round 17
// baseline (speedup 1.0000x reference)
#include <cuda_runtime.h>
#include <cuda_bf16.h>
#include <math.h>
#include <stdint.h>

// Problem dims
#define Bb 4
#define Tt 16
#define Ss 256
#define Dd 512
#define Nn 8
#define Ecols (Dd*Nn)     // 4096
#define Mrows (Bb*Ss)     // 1024
#define Kdim  Dd          // 512

typedef unsigned long long ull;

// ---------------- scratch (no allocation allowed -> __device__ globals) ----
__device__ __align__(16) float g_pop[Mrows * Ecols];  // sigmoid(pop response) [m,e] (16.8 MB)
__device__ __align__(16) float g_rate[Bb*Ss*Dd];
__device__ __align__(16) float g_phase[Bb*Ss*Dd];
__device__ __align__(16) int   g_st[Bb*Ss*Dd];
__device__ float g_w[4];
// split-bf16 operands, layout per row: [hi (512 bf16) | lo (512 bf16)] = 2KB/row
__device__ __align__(16) __nv_bfloat16 g_xa[Mrows * 2 * Kdim];   // 2 MB
__device__ __align__(16) __nv_bfloat16 g_wa[Ecols * 2 * Kdim];   // 8.4 MB
// packed rate/temporal/phase spike bits, 1B per (b,t,s,d)
__device__ __align__(16) unsigned char g_code[Bb*Tt*Ss*Dd];      // 33.5 MB

// ---------------- helpers ----------------
__device__ __forceinline__ float sigf(float x) {
    if (x >= 0.0f) { return 1.0f / (1.0f + expf(-x)); }
    float z = expf(x);
    return z / (1.0f + z);
}

__device__ __forceinline__ uint32_t smem_u32(const void* p) {
    uint32_t a;
    asm("{ .reg .u64 t; cvta.to.shared.u64 t, %1; cvt.u32.u64 %0, t; }" : "=r"(a) : "l"(p));
    return a;
}

__device__ __forceinline__ void cp16(uint32_t s, const void* g) {
    asm volatile("cp.async.cg.shared.global [%0], [%1], 16;" :: "r"(s), "l"(g) : "memory");
}

#define LDSM4(r, addr) \
    asm volatile("ldmatrix.sync.aligned.m8n8.x4.shared.b16 {%0,%1,%2,%3}, [%4];" \
        : "=r"((r)[0]), "=r"((r)[1]), "=r"((r)[2]), "=r"((r)[3]) : "r"(addr))

#define MMA16816(d, a, b0, b1) \
    asm volatile("mma.sync.aligned.m16n8k16.row.col.f32.bf16.bf16.f32 " \
        "{%0,%1,%2,%3}, {%4,%5,%6,%7}, {%8,%9}, {%0,%1,%2,%3};" \
        : "+f"((d)[0]), "+f"((d)[1]), "+f"((d)[2]), "+f"((d)[3]) \
        : "r"((a)[0]), "r"((a)[1]), "r"((a)[2]), "r"((a)[3]), "r"(b0), "r"(b1))

__device__ __forceinline__ ull pack4_hi(float4 v, float4& lo) {
    __nv_bfloat16 h0 = __float2bfloat16_rn(v.x);
    __nv_bfloat16 h1 = __float2bfloat16_rn(v.y);
    __nv_bfloat16 h2 = __float2bfloat16_rn(v.z);
    __nv_bfloat16 h3 = __float2bfloat16_rn(v.w);
    lo.x = v.x - __bfloat162float(h0);
    lo.y = v.y - __bfloat162float(h1);
    lo.z = v.z - __bfloat162float(h2);
    lo.w = v.w - __bfloat162float(h3);
    __nv_bfloat162 p0; p0.x = h0; p0.y = h1;
    __nv_bfloat162 p1; p1.x = h2; p1.y = h3;
    uint32_t u0 = *(uint32_t*)&p0, u1 = *(uint32_t*)&p1;
    return (ull)u0 | ((ull)u1 << 32);
}
__device__ __forceinline__ ull pack4(float4 v) {
    __nv_bfloat162 p0; p0.x = __float2bfloat16_rn(v.x); p0.y = __float2bfloat16_rn(v.y);
    __nv_bfloat162 p1; p1.x = __float2bfloat16_rn(v.z); p1.y = __float2bfloat16_rn(v.w);
    uint32_t u0 = *(uint32_t*)&p0, u1 = *(uint32_t*)&p1;
    return (ull)u0 | ((ull)u1 << 32);
}

// ---------------- kernel 1: prep (vectorized x4) + split_x + softmax ------
__global__ __launch_bounds__(256) void prep_kernel(
    const float* __restrict__ x,
    const float* __restrict__ noise,
    const float* __restrict__ ew)
{
    int i = blockIdx.x * blockDim.x + threadIdx.x;     // quad id, 131072 total
    float4 xv = *(const float4*)&x[i * 4];
    float4 nv = *(const float4*)&noise[i * 4];

    float s0 = sigf(xv.x), s1 = sigf(xv.y), s2 = sigf(xv.z), s3 = sigf(xv.w);

    float4 rv;
    rv.x = fminf(fmaxf(s0 * 0.9f + 0.05f + nv.x * 0.1f, 0.0f), 1.0f);
    rv.y = fminf(fmaxf(s1 * 0.9f + 0.05f + nv.y * 0.1f, 0.0f), 1.0f);
    rv.z = fminf(fmaxf(s2 * 0.9f + 0.05f + nv.z * 0.1f, 0.0f), 1.0f);
    rv.w = fminf(fmaxf(s3 * 0.9f + 0.05f + nv.w * 0.1f, 0.0f), 1.0f);
    *(float4*)&g_rate[i * 4] = rv;

    int4 st;
    st.x = (int)(s0 * 15.0f); st.y = (int)(s1 * 15.0f);
    st.z = (int)(s2 * 15.0f); st.w = (int)(s3 * 15.0f);
    *(int4*)&g_st[i * 4] = st;

    float4 ph;
    ph.x = s0 * 6.2831855f; ph.y = s1 * 6.2831855f;
    ph.z = s2 * 6.2831855f; ph.w = s3 * 6.2831855f;
    *(float4*)&g_phase[i * 4] = ph;

    // X split: row m, [hi|lo] halves of 512 bf16 each = 128 ull each
    int m = i >> 7, q = i & 127;
    float4 lo; ull hi = pack4_hi(xv, lo); ull lp = pack4(lo);
    ull* row = (ull*)&g_xa[(size_t)m * 2 * Kdim];
    row[q] = hi; row[128 + q] = lp;

    if (i == 0) {
        float m2 = fmaxf(fmaxf(ew[0], ew[1]), fmaxf(ew[2], ew[3]));
        float e0 = expf(ew[0]-m2), e1 = expf(ew[1]-m2), e2 = expf(ew[2]-m2), e3 = expf(ew[3]-m2);
        float s = e0 + e1 + e2 + e3;
        g_w[0] = e0/s; g_w[1] = e1/s; g_w[2] = e2/s; g_w[3] = e3/s;
    }
}

// ---------------- kernel 1b: split W -> [hi|lo] ---------------------------
__global__ __launch_bounds__(256) void split_w_kernel(const float* __restrict__ W)
{
    int i = blockIdx.x * blockDim.x + threadIdx.x;     // quad id, 4096*128
    int n = i >> 7, q = i & 127;
    float4 v = *(const float4*)&W[n * Kdim + (q << 2)];
    float4 lo; ull hi = pack4_hi(v, lo); ull lp = pack4(lo);
    ull* row = (ull*)&g_wa[(size_t)n * 2 * Kdim];
    row[q] = hi; row[128 + q] = lp;
}

// ---------------- kernel 1c: rate/temporal/phase spikes -> 3-bit code -----
// Runs on a forked stream, CONCURRENT with split_w + gemm (no dependency).
// One thread per (b,t,s,4d): reads rrate float4, writes uchar4 codes.
__global__ __launch_bounds__(256) void fuse_partial_kernel(
    const float* __restrict__ freq,
    const float* __restrict__ rrate)
{
    int q = blockIdx.x * blockDim.x + threadIdx.x;   // [B,T,S,D/4]
    int dq = q & 127;
    int s  = (q >> 7) & (Ss - 1);
    int t  = (q >> 15) & (Tt - 1);
    int b  = q >> 19;
    int d  = dq << 2;
    int bsd = (b * Ss + s) * Dd + d;
    int i  = ((b * Tt + t) * Ss + s) * Dd + d;

    float4 rr = *(const float4*)&rrate[i];
    float4 rate = *(const float4*)&g_rate[bsd];
    int4   st = *(const int4*)&g_st[bsd];
    float4 ph = *(const float4*)&g_phase[bsd];
    float4 fd = *(const float4*)&freq[d];

    const float tstep = 6.2831855f / 15.0f;
    float tt = (float)t * tstep;

    uchar4 c;
    c.x = (unsigned char)((rr.x < rate.x ? 1 : 0) | (t == st.x ? 2 : 0)
          | (sinf(fd.x * tt + ph.x) > 0.5f ? 4 : 0));
    c.y = (unsigned char)((rr.y < rate.y ? 1 : 0) | (t == st.y ? 2 : 0)
          | (sinf(fd.y * tt + ph.y) > 0.5f ? 4 : 0));
    c.z = (unsigned char)((rr.z < rate.z ? 1 : 0) | (t == st.z ? 2 : 0)
          | (sinf(fd.z * tt + ph.z) > 0.5f ? 4 : 0));
    c.w = (unsigned char)((rr.w < rate.w ? 1 : 0) | (t == st.w ? 2 : 0)
          | (sinf(fd.w * tt + ph.w) > 0.5f ? 4 : 0));
    *(uchar4*)&g_code[i] = c;
}

// ---------------- kernel 2: low-traffic 3-product split GEMM (R16) --------
#define BM 128
#define BN 128
#define BK 32
#define NIT (Kdim/BK)        // 16
#define SSTR 80              // 64B data + 16B pad: conflict-free ldmatrix
#define SUBT (128*SSTR)      // 10240 B per sub-tile
#define STAGE (4*SUBT)       // 40960 B : [Ahi, Alo, Bhi, Blo]
#define SMEM_GEMM (2*STAGE)  // 81920 B

__global__ __launch_bounds__(256, 2) void gemm_mma_kernel(const float* __restrict__ bias)
{
    extern __shared__ __align__(16) char sm_dyn[];
    const uint32_t sbase = smem_u32(sm_dyn);
    const int tid = threadIdx.x;
    const int w = tid >> 5, l = tid & 31;
    const int wm = w & 3, wn = w >> 2;             // 4x2 warp grid, warp tile 32x64
    const int m0 = blockIdx.y * BM, n0 = blockIdx.x * BN;

    float acc[2][8][4];
    #pragma unroll
    for (int mt = 0; mt < 2; mt++)
        #pragma unroll
        for (int nt = 0; nt < 8; nt++)
            #pragma unroll
            for (int j = 0; j < 4; j++) acc[mt][nt][j] = 0.0f;

    const int lr = l & 15, lh = l >> 4;
    uint32_t aoff[2], boff[4];
    #pragma unroll
    for (int mt = 0; mt < 2; mt++) aoff[mt] = (uint32_t)((wm*32 + mt*16 + lr) * SSTR + lh*16);
    #pragma unroll
    for (int np = 0; np < 4; np++) boff[np] = (uint32_t)((wn*64 + np*16 + lr) * SSTR + lh*16);

    const int r1 = tid >> 2, kc = tid & 3;
    const char* gx1 = (const char*)g_xa + (size_t)(m0 + r1)      * 2048 + kc * 16;
    const char* gx2 = (const char*)g_xa + (size_t)(m0 + r1 + 64) * 2048 + kc * 16;
    const char* gw1 = (const char*)g_wa + (size_t)(n0 + r1)      * 2048 + kc * 16;
    const char* gw2 = (const char*)g_wa + (size_t)(n0 + r1 + 64) * 2048 + kc * 16;
    const uint32_t so1 = (uint32_t)(r1 * SSTR + kc * 16);
    const uint32_t so2 = so1 + 64u * SSTR;

    auto load_stage = [&](int buf) {
        const uint32_t bs = sbase + (uint32_t)(buf * STAGE);
        cp16(bs + so1,            gx1);          // Ahi
        cp16(bs + so2,            gx2);
        cp16(bs + SUBT + so1,     gx1 + 1024);   // Alo
        cp16(bs + SUBT + so2,     gx2 + 1024);
        cp16(bs + 2*SUBT + so1,   gw1);          // Bhi
        cp16(bs + 2*SUBT + so2,   gw2);
        cp16(bs + 3*SUBT + so1,   gw1 + 1024);   // Blo
        cp16(bs + 3*SUBT + so2,   gw2 + 1024);
        asm volatile("cp.async.commit_group;" ::: "memory");
        gx1 += 64; gx2 += 64; gw1 += 64; gw2 += 64;   // advance 32 bf16
    };

    load_stage(0);

    for (int kt = 0; kt < NIT; kt++) {
        const int buf = kt & 1;
        asm volatile("cp.async.wait_group 0;" ::: "memory");
        __syncthreads();
        if (kt + 1 < NIT) load_stage(buf ^ 1);   // overlaps compute below

        const uint32_t sAhi = sbase + (uint32_t)(buf * STAGE);
        const uint32_t sAlo = sAhi + SUBT;
        const uint32_t sBhi = sAhi + 2*SUBT;
        const uint32_t sBlo = sAhi + 3*SUBT;
        #pragma unroll
        for (int kk = 0; kk < 2; kk++) {           // two k16 steps per BK=32
            uint32_t ah[2][4], al[2][4];
            #pragma unroll
            for (int mt = 0; mt < 2; mt++) {
                LDSM4(ah[mt], sAhi + aoff[mt] + kk*32);
                LDSM4(al[mt], sAlo + aoff[mt] + kk*32);
            }
            #pragma unroll
            for (int np = 0; np < 4; np++) {
                uint32_t bh[4], bl[4];
                LDSM4(bh, sBhi + boff[np] + kk*32);
                LDSM4(bl, sBlo + boff[np] + kk*32);
                #pragma unroll
                for (int mt = 0; mt < 2; mt++) {
                    MMA16816(acc[mt][np*2],     ah[mt], bh[0], bh[2]);   // hh
                    MMA16816(acc[mt][np*2 + 1], ah[mt], bh[1], bh[3]);
                    MMA16816(acc[mt][np*2],     ah[mt], bl[0], bl[2]);   // hl
                    MMA16816(acc[mt][np*2 + 1], ah[mt], bl[1], bl[3]);
                    MMA16816(acc[mt][np*2],     al[mt], bh[0], bh[2]);   // lh
                    MMA16816(acc[mt][np*2 + 1], al[mt], bh[1], bh[3]);
                }
            }
        }
    }

    // epilogue: bias + stable sigmoid, write g_pop
    #pragma unroll
    for (int mt = 0; mt < 2; mt++) {
        int row = m0 + wm*32 + mt*16 + (l >> 2);
        #pragma unroll
        for (int nt = 0; nt < 8; nt++) {
            int col = n0 + wn*64 + nt*8 + 2*(l & 3);
            float2 bb = *(const float2*)&bias[col];
            float2 o0, o1;
            o0.x = sigf(acc[mt][nt][0] + bb.x);
            o0.y = sigf(acc[mt][nt][1] + bb.y);
            o1.x = sigf(acc[mt][nt][2] + bb.x);
            o1.y = sigf(acc[mt][nt][3] + bb.y);
            *(float2*)&g_pop[(size_t)row * Ecols + col] = o0;
            *(float2*)&g_pop[(size_t)(row + 8) * Ecols + col] = o1;
        }
    }
}

// ---------------- kernel 3: population spikes + final combine (t-quad) ----
// Reads packed codes instead of recomputing rate/temporal/phase:
// drops the rrate stream (33.5MB) from the critical pass.
__global__ __launch_bounds__(256) void fuse_pop_kernel(
    const float* __restrict__ rpop,
    float* __restrict__ out)
{
    int idx = blockIdx.x * blockDim.x + threadIdx.x;   // [B, 4, S, D] linear
    int d  = idx & (Dd - 1);
    int s  = (idx >> 9) & (Ss - 1);
    int th = (idx >> 17) & 3;        // t quarter: t = th + 4*j
    int b  = idx >> 19;
    int bsd = (b * Ss + s) * Dd + d;
    int i0 = ((b * Tt + th) * Ss + s) * Dd + d;
    const int TS = 4 * Ss * Dd;      // t-step of 4 in elements

    float w0 = g_w[0], w1 = g_w[1], w2 = g_w[2], w3 = g_w[3];

    const float4* pr4 = (const float4*)g_pop + (size_t)bsd * 2;
    float4 p0 = pr4[0], p1 = pr4[1];

    // issue all rand_pop + code loads up front (MLP)
    float4 q0[4], q1[4];
    unsigned int cd[4];
    #pragma unroll
    for (int j = 0; j < 4; j++) {
        const float4* rp4 = (const float4*)rpop + (size_t)(i0 + j * TS) * 2;
        q0[j] = rp4[0];
        q1[j] = rp4[1];
        cd[j] = g_code[i0 + j * TS];
    }

    #pragma unroll
    for (int j = 0; j < 4; j++) {
        int cnt = (q0[j].x < p0.x) + (q0[j].y < p0.y) + (q0[j].z < p0.z) + (q0[j].w < p0.w)
                + (q1[j].x < p1.x) + (q1[j].y < p1.y) + (q1[j].z < p1.z) + (q1[j].w < p1.w);
        float rs = (cd[j] & 1u) ? 1.0f : 0.0f;
        float ts = (cd[j] & 2u) ? 1.0f : 0.0f;
        float ps = (cd[j] & 4u) ? 1.0f : 0.0f;
        float o = w0 * rs
                + w1 * ts
                + w2 * ((float)cnt * 0.125f)
                + w3 * ps;
        out[i0 + j * TS] = o;
    }
}

// ---------------- launch ---------------------------------------------------
extern "C" void kernel_launch(void* const* d_in, const int* in_sizes, int n_in,
                              void* d_out, int out_size)
{
    const float* x     = (const float*)d_in[0];  // [B,S,D]
    const float* freq  = (const float*)d_in[1];  // [D]
    const float* pw    = (const float*)d_in[2];  // [D*N, D]
    const float* pb    = (const float*)d_in[3];  // [D*N]
    const float* ew    = (const float*)d_in[4];  // [4]
    const float* noise = (const float*)d_in[5];  // [B,S,D]
    const float* rr    = (const float*)d_in[6];  // [B,T,S,D]
    const float* rp    = (const float*)d_in[7];  // [B,T,S,D,N]
    float* out = (float*)d_out;                  // [B,T,S,D]

    // one-time infra (host-side resources only; no device memory).
    // First call is the (non-captured) correctness run, so creation
    // never happens during graph capture; captured calls reuse handles.
    static cudaStream_t s2 = nullptr;
    static cudaEvent_t evA = nullptr, evB = nullptr;
    if (s2 == nullptr) {
        cudaStreamCreateWithFlags(&s2, cudaStreamNonBlocking);
        cudaEventCreateWithFlags(&evA, cudaEventDisableTiming);
        cudaEventCreateWithFlags(&evB, cudaEventDisableTiming);
    }

    cudaFuncSetAttribute(gemm_mma_kernel,
                         cudaFuncAttributeMaxDynamicSharedMemorySize, SMEM_GEMM);

    // stream 0:  prep -> split_w -> gemm ----------------.
    // stream s2:        fuse_partial (after prep) --------+--> fuse_pop
    prep_kernel<<<(Bb*Ss*Dd/4) / 256, 256>>>(x, noise, ew);
    cudaEventRecord(evA, 0);
    cudaStreamWaitEvent(s2, evA, 0);
    fuse_partial_kernel<<<(Bb*Tt*Ss*Dd/4) / 256, 256, 0, s2>>>(freq, rr);
    cudaEventRecord(evB, s2);

    split_w_kernel<<<(Ecols*Kdim/4) / 256, 256>>>(pw);
    gemm_mma_kernel<<<dim3(Ecols / BN, Mrows / BM), 256, SMEM_GEMM>>>(pb);

    cudaStreamWaitEvent(0, evB, 0);
    fuse_pop_kernel<<<(Bb*(Tt/4)*Ss*Dd) / 256, 256>>>(rp, out);
}